// round 1
// baseline (speedup 1.0000x reference)
#include <cuda_runtime.h>
#include <cuda_bf16.h>
#include <math.h>

#define N_PTS   (1 << 19)
#define N_GRIDS 64
#define DIM     64
#define CH_OFF  262144   // 64*64*64

typedef unsigned long long u64;

// ---------- packed f32x2 helpers (FFMA2 path: ptxas never emits it from C++) ----------
__device__ __forceinline__ u64 pack2(float lo, float hi) {
    u64 r; asm("mov.b64 %0, {%1, %2};" : "=l"(r) : "f"(lo), "f"(hi)); return r;
}
__device__ __forceinline__ void unpack2(u64 v, float& lo, float& hi) {
    asm("mov.b64 {%0, %1}, %2;" : "=f"(lo), "=f"(hi) : "l"(v));
}
__device__ __forceinline__ u64 ffma2(u64 a, u64 b, u64 c) {
    u64 d; asm("fma.rn.f32x2 %0, %1, %2, %3;" : "=l"(d) : "l"(a), "l"(b), "l"(c)); return d;
}

// ---------- device scratch (allocation-free rule: __device__ globals) ----------
__device__ float  g_xf[N_GRIDS * 12];   // per-grid: M = diag(s)*R (9) + t (3)
__device__ float2 g_w0p[128 * 32];      // [k][j2] -> (W0[2*j2][k], W0[2*j2+1][k])
__device__ float2 g_w1p[64 * 32];       // [k][j2] -> (W1[2*j2][k], W1[2*j2+1][k])
__device__ float2 g_w2p[32];            // (W2[2*j2], W2[2*j2+1])

// ---------- prep: transforms + weight pair-packing (runs every launch, tiny) ----------
__global__ void amgsrn_prep(const float* __restrict__ r, const float* __restrict__ s,
                            const float* __restrict__ t,
                            const float* __restrict__ W0, const float* __restrict__ W1,
                            const float* __restrict__ W2) {
    int tid = threadIdx.x;
    if (tid < N_GRIDS) {
        int g = tid;
        float qw = r[g*4+0], qx = r[g*4+1], qy = r[g*4+2], qz = r[g*4+3];
        float inv = rsqrtf(qw*qw + qx*qx + qy*qy + qz*qz);
        qw *= inv; qx *= inv; qy *= inv; qz *= inv;
        float sx = s[g*3+0], sy = s[g*3+1], sz = s[g*3+2];
        float* X = &g_xf[g*12];
        X[0] = sx * (1.0f - 2.0f*(qy*qy + qz*qz));
        X[1] = sx * (2.0f*(qx*qy - qw*qz));
        X[2] = sx * (2.0f*(qx*qz + qw*qy));
        X[3] = sy * (2.0f*(qx*qy + qw*qz));
        X[4] = sy * (1.0f - 2.0f*(qx*qx + qz*qz));
        X[5] = sy * (2.0f*(qy*qz - qw*qx));
        X[6] = sz * (2.0f*(qx*qz - qw*qy));
        X[7] = sz * (2.0f*(qy*qz + qw*qx));
        X[8] = sz * (1.0f - 2.0f*(qx*qx + qy*qy));
        X[9]  = t[g*3+0];
        X[10] = t[g*3+1];
        X[11] = t[g*3+2];
    }
    for (int i = tid; i < 128*32; i += blockDim.x) {
        int k = i >> 5, j2 = i & 31;
        g_w0p[i] = make_float2(W0[(2*j2)*128 + k], W0[(2*j2+1)*128 + k]);
    }
    for (int i = tid; i < 64*32; i += blockDim.x) {
        int k = i >> 5, j2 = i & 31;
        g_w1p[i] = make_float2(W1[(2*j2)*64 + k], W1[(2*j2+1)*64 + k]);
    }
    if (tid < 32) g_w2p[tid] = make_float2(W2[2*tid], W2[2*tid+1]);
}

// ---------- main fused kernel: encode + MLP, one point per thread ----------
__global__ void __launch_bounds__(128, 3)
amgsrn_main(const float* __restrict__ x, const float* __restrict__ features,
            float* __restrict__ out) {
    extern __shared__ float smem[];
    u64*   w0 = (u64*)smem;             // 4096 u64 (32 KB)
    u64*   w1 = w0 + 4096;              // 2048 u64 (16 KB)
    u64*   w2 = w1 + 2048;              // 32 u64 (256 B)
    float* xf = (float*)(w2 + 32);      // 768 floats (3 KB)

    int tid = threadIdx.x;
    {
        const u64* s0 = (const u64*)g_w0p;
        for (int i = tid; i < 4096; i += 128) w0[i] = s0[i];
        const u64* s1 = (const u64*)g_w1p;
        for (int i = tid; i < 2048; i += 128) w1[i] = s1[i];
        if (tid < 32) w2[tid] = ((const u64*)g_w2p)[tid];
        for (int i = tid; i < 768; i += 128) xf[i] = g_xf[i];
    }
    __syncthreads();

    int p = blockIdx.x * 128 + tid;
    float px = x[3*p+0], py = x[3*p+1], pz = x[3*p+2];

    u64 acc0[32];
#pragma unroll
    for (int j = 0; j < 32; ++j) acc0[j] = 0ull;

    for (int g = 0; g < N_GRIDS; ++g) {
        const float* X = &xf[g*12];
        float tpx = fmaf(X[0], px, fmaf(X[1], py, fmaf(X[2], pz, X[9])));
        float tpy = fmaf(X[3], px, fmaf(X[4], py, fmaf(X[5], pz, X[10])));
        float tpz = fmaf(X[6], px, fmaf(X[7], py, fmaf(X[8], pz, X[11])));
        float gx = (tpx + 1.0f) * 31.5f;
        float gy = (tpy + 1.0f) * 31.5f;
        float gz = (tpz + 1.0f) * 31.5f;
        bool inb = (gx > -1.0f) && (gx < 64.0f) &&
                   (gy > -1.0f) && (gy < 64.0f) &&
                   (gz > -1.0f) && (gz < 64.0f);
        unsigned m = __ballot_sync(0xffffffffu, inb);
        if (!m) continue;   // whole warp misses this grid

        float f0 = 0.0f, f1 = 0.0f;
        if (inb) {
            float x0f = floorf(gx), y0f = floorf(gy), z0f = floorf(gz);
            float fx = gx - x0f, fy = gy - y0f, fz = gz - z0f;
            int x0 = (int)x0f, y0 = (int)y0f, z0 = (int)z0f;
            float wx0 = (x0 >= 0) ? (1.0f - fx) : 0.0f;
            float wx1 = (x0 < 63) ? fx : 0.0f;
            float wy0 = (y0 >= 0) ? (1.0f - fy) : 0.0f;
            float wy1 = (y0 < 63) ? fy : 0.0f;
            float wz0 = (z0 >= 0) ? (1.0f - fz) : 0.0f;
            float wz1 = (z0 < 63) ? fz : 0.0f;
            int x0c = max(x0, 0), x1c = min(x0 + 1, 63);
            int y0c = max(y0, 0), y1c = min(y0 + 1, 63);
            int z0c = max(z0, 0), z1c = min(z0 + 1, 63);

            const float* b0 = features + ((size_t)g << 19);
            const float* b1 = b0 + CH_OFF;
            int r00 = (z0c << 12) + (y0c << 6);
            int r01 = (z0c << 12) + (y1c << 6);
            int r10 = (z1c << 12) + (y0c << 6);
            int r11 = (z1c << 12) + (y1c << 6);

            float a000 = __ldg(b0 + r00 + x0c), a001 = __ldg(b0 + r00 + x1c);
            float a010 = __ldg(b0 + r01 + x0c), a011 = __ldg(b0 + r01 + x1c);
            float a100 = __ldg(b0 + r10 + x0c), a101 = __ldg(b0 + r10 + x1c);
            float a110 = __ldg(b0 + r11 + x0c), a111 = __ldg(b0 + r11 + x1c);
            float c000 = __ldg(b1 + r00 + x0c), c001 = __ldg(b1 + r00 + x1c);
            float c010 = __ldg(b1 + r01 + x0c), c011 = __ldg(b1 + r01 + x1c);
            float c100 = __ldg(b1 + r10 + x0c), c101 = __ldg(b1 + r10 + x1c);
            float c110 = __ldg(b1 + r11 + x0c), c111 = __ldg(b1 + r11 + x1c);

            f0 = wz0 * (wy0 * (wx0*a000 + wx1*a001) + wy1 * (wx0*a010 + wx1*a011))
               + wz1 * (wy0 * (wx0*a100 + wx1*a101) + wy1 * (wx0*a110 + wx1*a111));
            f1 = wz0 * (wy0 * (wx0*c000 + wx1*c001) + wy1 * (wx0*c010 + wx1*c011))
               + wz1 * (wy0 * (wx0*c100 + wx1*c101) + wy1 * (wx0*c110 + wx1*c111));
        }

        // layer-0 accumulate: h0[j] += f0*W0[j][2g] + f1*W0[j][2g+1], j-pairs via FFMA2
        u64 f00 = pack2(f0, f0);
        u64 f11 = pack2(f1, f1);
        const u64* r0 = &w0[g << 6];      // row k = 2g
        const u64* r1 = r0 + 32;          // row k = 2g+1
#pragma unroll
        for (int j = 0; j < 32; ++j)
            acc0[j] = ffma2(f00, r0[j], ffma2(f11, r1[j], acc0[j]));
    }

    // relu -> h0
    float h0[64];
#pragma unroll
    for (int j = 0; j < 32; ++j) {
        float lo, hi; unpack2(acc0[j], lo, hi);
        h0[2*j]   = fmaxf(lo, 0.0f);
        h0[2*j+1] = fmaxf(hi, 0.0f);
    }

    // layer 1
    u64 acc1[32];
#pragma unroll
    for (int j = 0; j < 32; ++j) acc1[j] = 0ull;
#pragma unroll
    for (int k = 0; k < 64; ++k) {
        u64 hk = pack2(h0[k], h0[k]);
        const u64* row = &w1[k << 5];
#pragma unroll
        for (int j = 0; j < 32; ++j)
            acc1[j] = ffma2(hk, row[j], acc1[j]);
    }

    // layer 2
    float res = 0.0f;
#pragma unroll
    for (int j = 0; j < 32; ++j) {
        float lo, hi;  unpack2(acc1[j], lo, hi);
        float wl, wh;  unpack2(w2[j], wl, wh);
        res = fmaf(fmaxf(lo, 0.0f), wl, res);
        res = fmaf(fmaxf(hi, 0.0f), wh, res);
    }
    out[p] = res;
}

extern "C" void kernel_launch(void* const* d_in, const int* in_sizes, int n_in,
                              void* d_out, int out_size) {
    const float* x        = (const float*)d_in[0];
    const float* r        = (const float*)d_in[1];
    const float* s        = (const float*)d_in[2];
    const float* t        = (const float*)d_in[3];
    const float* features = (const float*)d_in[4];
    const float* W0       = (const float*)d_in[5];
    const float* W1       = (const float*)d_in[6];
    const float* W2       = (const float*)d_in[7];
    float* out = (float*)d_out;

    const int smem_bytes = 4096*8 + 2048*8 + 32*8 + 768*4;  // 52480
    cudaFuncSetAttribute(amgsrn_main, cudaFuncAttributeMaxDynamicSharedMemorySize, smem_bytes);

    amgsrn_prep<<<1, 256>>>(r, s, t, W0, W1, W2);
    amgsrn_main<<<N_PTS / 128, 128, smem_bytes>>>(x, features, out);
}

// round 2
// speedup vs baseline: 1.9758x; 1.9758x over previous
#include <cuda_runtime.h>
#include <cuda_fp16.h>
#include <math.h>

#define N_PTS   (1 << 19)
#define N_GRIDS 64
#define CH_OFF  262144   // 64*64*64
#define NB      32768    // 32^3 morton buckets

typedef unsigned long long u64;

// ---------- packed f32x2 helpers ----------
__device__ __forceinline__ u64 pack2(float lo, float hi) {
    u64 r; asm("mov.b64 %0, {%1, %2};" : "=l"(r) : "f"(lo), "f"(hi)); return r;
}
__device__ __forceinline__ void unpack2(u64 v, float& lo, float& hi) {
    asm("mov.b64 {%0, %1}, %2;" : "=f"(lo), "=f"(hi) : "l"(v));
}
__device__ __forceinline__ u64 ffma2(u64 a, u64 b, u64 c) {
    u64 d; asm("fma.rn.f32x2 %0, %1, %2, %3;" : "=l"(d) : "l"(a), "l"(b), "l"(c)); return d;
}

// ---------- device scratch ----------
__device__ float   g_xf[N_GRIDS * 12];
__device__ float2  g_w0p[128 * 32];
__device__ float2  g_w1p[64 * 32];
__device__ float2  g_w2p[32];
__device__ __half2 g_feat16[N_GRIDS * CH_OFF];   // 67 MB: [g][zyx] -> (c0,c1)
__device__ int     g_hist[NB];
__device__ int     g_off[NB];
__device__ int     g_perm[N_PTS];
__device__ float4  g_xs[N_PTS];

// ---------- prep: transforms + weight pair-packing ----------
__global__ void amgsrn_prep(const float* __restrict__ r, const float* __restrict__ s,
                            const float* __restrict__ t,
                            const float* __restrict__ W0, const float* __restrict__ W1,
                            const float* __restrict__ W2) {
    int tid = threadIdx.x;
    if (tid < N_GRIDS) {
        int g = tid;
        float qw = r[g*4+0], qx = r[g*4+1], qy = r[g*4+2], qz = r[g*4+3];
        float inv = rsqrtf(qw*qw + qx*qx + qy*qy + qz*qz);
        qw *= inv; qx *= inv; qy *= inv; qz *= inv;
        float sx = s[g*3+0], sy = s[g*3+1], sz = s[g*3+2];
        float* X = &g_xf[g*12];
        X[0] = sx * (1.0f - 2.0f*(qy*qy + qz*qz));
        X[1] = sx * (2.0f*(qx*qy - qw*qz));
        X[2] = sx * (2.0f*(qx*qz + qw*qy));
        X[3] = sy * (2.0f*(qx*qy + qw*qz));
        X[4] = sy * (1.0f - 2.0f*(qx*qx + qz*qz));
        X[5] = sy * (2.0f*(qy*qz - qw*qx));
        X[6] = sz * (2.0f*(qx*qz - qw*qy));
        X[7] = sz * (2.0f*(qy*qz + qw*qx));
        X[8] = sz * (1.0f - 2.0f*(qx*qx + qy*qy));
        X[9]  = t[g*3+0];
        X[10] = t[g*3+1];
        X[11] = t[g*3+2];
    }
    for (int i = tid; i < 128*32; i += blockDim.x) {
        int k = i >> 5, j2 = i & 31;
        g_w0p[i] = make_float2(W0[(2*j2)*128 + k], W0[(2*j2+1)*128 + k]);
    }
    for (int i = tid; i < 64*32; i += blockDim.x) {
        int k = i >> 5, j2 = i & 31;
        g_w1p[i] = make_float2(W1[(2*j2)*64 + k], W1[(2*j2+1)*64 + k]);
    }
    if (tid < 32) g_w2p[tid] = make_float2(W2[2*tid], W2[2*tid+1]);
}

// ---------- feature relayout: [g][c][zyx] fp32 -> [g][zyx] half2 ----------
__global__ void amgsrn_relayout(const float* __restrict__ features) {
    int i = blockIdx.x * 256 + threadIdx.x;          // 0 .. 64*262144-1
    int g = i >> 18;
    int v = i & (CH_OFF - 1);
    const float* b = features + (((size_t)g * 2) << 18) + v;
    g_feat16[i] = __floats2half2_rn(b[0], b[CH_OFF]);
}

// ---------- sort: morton bucket counting-sort ----------
__device__ __forceinline__ unsigned expand_bits(unsigned v) {
    v &= 0x3ff;
    v = (v | (v << 16)) & 0x030000FF;
    v = (v | (v << 8))  & 0x0300F00F;
    v = (v | (v << 4))  & 0x030C30C3;
    v = (v | (v << 2))  & 0x09249249;
    return v;
}
__device__ __forceinline__ int morton_bucket(float px, float py, float pz) {
    unsigned ux = (unsigned)min(max((int)((px + 1.0f) * 16.0f), 0), 31);
    unsigned uy = (unsigned)min(max((int)((py + 1.0f) * 16.0f), 0), 31);
    unsigned uz = (unsigned)min(max((int)((pz + 1.0f) * 16.0f), 0), 31);
    return (int)(expand_bits(ux) | (expand_bits(uy) << 1) | (expand_bits(uz) << 2));
}

__global__ void amgsrn_zero_hist() {
    int i = blockIdx.x * 256 + threadIdx.x;
    if (i < NB) g_hist[i] = 0;
}
__global__ void amgsrn_hist(const float* __restrict__ x) {
    int p = blockIdx.x * 256 + threadIdx.x;
    int b = morton_bucket(x[3*p], x[3*p+1], x[3*p+2]);
    atomicAdd(&g_hist[b], 1);
}
__global__ void amgsrn_scan() {
    __shared__ int partial[1024];
    int tid = threadIdx.x;
    int base = tid * 32;
    int loc[32];
    int sum = 0;
#pragma unroll
    for (int i = 0; i < 32; ++i) { loc[i] = sum; sum += g_hist[base + i]; }
    partial[tid] = sum;
    __syncthreads();
    for (int d = 1; d < 1024; d <<= 1) {
        int v = 0;
        if (tid >= d) v = partial[tid - d];
        __syncthreads();
        if (tid >= d) partial[tid] += v;
        __syncthreads();
    }
    int off = (tid > 0) ? partial[tid - 1] : 0;
#pragma unroll
    for (int i = 0; i < 32; ++i) g_off[base + i] = off + loc[i];
}
__global__ void amgsrn_scatter(const float* __restrict__ x) {
    int p = blockIdx.x * 256 + threadIdx.x;
    float px = x[3*p], py = x[3*p+1], pz = x[3*p+2];
    int b = morton_bucket(px, py, pz);
    int pos = atomicAdd(&g_off[b], 1);
    g_perm[pos] = p;
    g_xs[pos] = make_float4(px, py, pz, 0.0f);
}

// ---------- main fused kernel: encode + MLP, one sorted point per thread ----------
__global__ void __launch_bounds__(128, 3)
amgsrn_main(const float* __restrict__ out_unused, float* __restrict__ out) {
    extern __shared__ float smem[];
    u64*   w0 = (u64*)smem;             // 4096 u64 (32 KB)
    u64*   w1 = w0 + 4096;              // 2048 u64 (16 KB)
    u64*   w2 = w1 + 2048;              // 32 u64
    float* xf = (float*)(w2 + 32);      // 768 floats

    int tid = threadIdx.x;
    {
        const u64* s0 = (const u64*)g_w0p;
        for (int i = tid; i < 4096; i += 128) w0[i] = s0[i];
        const u64* s1 = (const u64*)g_w1p;
        for (int i = tid; i < 2048; i += 128) w1[i] = s1[i];
        if (tid < 32) w2[tid] = ((const u64*)g_w2p)[tid];
        for (int i = tid; i < 768; i += 128) xf[i] = g_xf[i];
    }
    __syncthreads();

    int i = blockIdx.x * 128 + tid;
    float4 pt = g_xs[i];
    float px = pt.x, py = pt.y, pz = pt.z;
    int pdst = g_perm[i];

    u64 acc0[32];
#pragma unroll
    for (int j = 0; j < 32; ++j) acc0[j] = 0ull;

    for (int g = 0; g < N_GRIDS; ++g) {
        const float* X = &xf[g*12];
        float tpx = fmaf(X[0], px, fmaf(X[1], py, fmaf(X[2], pz, X[9])));
        float tpy = fmaf(X[3], px, fmaf(X[4], py, fmaf(X[5], pz, X[10])));
        float tpz = fmaf(X[6], px, fmaf(X[7], py, fmaf(X[8], pz, X[11])));
        float gx = (tpx + 1.0f) * 31.5f;
        float gy = (tpy + 1.0f) * 31.5f;
        float gz = (tpz + 1.0f) * 31.5f;
        bool inb = (gx > -1.0f) && (gx < 64.0f) &&
                   (gy > -1.0f) && (gy < 64.0f) &&
                   (gz > -1.0f) && (gz < 64.0f);
        unsigned m = __ballot_sync(0xffffffffu, inb);
        if (!m) continue;   // whole warp misses this grid (coherent after sort)

        float f0 = 0.0f, f1 = 0.0f;
        if (inb) {
            float x0f = floorf(gx), y0f = floorf(gy), z0f = floorf(gz);
            float fx = gx - x0f, fy = gy - y0f, fz = gz - z0f;
            int x0 = (int)x0f, y0 = (int)y0f, z0 = (int)z0f;
            float wx0 = (x0 >= 0) ? (1.0f - fx) : 0.0f;
            float wx1 = (x0 < 63) ? fx : 0.0f;
            float wy0 = (y0 >= 0) ? (1.0f - fy) : 0.0f;
            float wy1 = (y0 < 63) ? fy : 0.0f;
            float wz0 = (z0 >= 0) ? (1.0f - fz) : 0.0f;
            float wz1 = (z0 < 63) ? fz : 0.0f;
            int x0c = max(x0, 0), x1c = min(x0 + 1, 63);
            int y0c = max(y0, 0), y1c = min(y0 + 1, 63);
            int z0c = max(z0, 0), z1c = min(z0 + 1, 63);

            const __half2* fb = g_feat16 + ((size_t)g << 18);
            int r00 = (z0c << 12) + (y0c << 6);
            int r01 = (z0c << 12) + (y1c << 6);
            int r10 = (z1c << 12) + (y0c << 6);
            int r11 = (z1c << 12) + (y1c << 6);

            float2 v000 = __half22float2(__ldg(fb + r00 + x0c));
            float2 v001 = __half22float2(__ldg(fb + r00 + x1c));
            float2 v010 = __half22float2(__ldg(fb + r01 + x0c));
            float2 v011 = __half22float2(__ldg(fb + r01 + x1c));
            float2 v100 = __half22float2(__ldg(fb + r10 + x0c));
            float2 v101 = __half22float2(__ldg(fb + r10 + x1c));
            float2 v110 = __half22float2(__ldg(fb + r11 + x0c));
            float2 v111 = __half22float2(__ldg(fb + r11 + x1c));

            float wy0z0 = wy0 * wz0, wy1z0 = wy1 * wz0;
            float wy0z1 = wy0 * wz1, wy1z1 = wy1 * wz1;
            float w000 = wx0 * wy0z0, w001 = wx1 * wy0z0;
            float w010 = wx0 * wy1z0, w011 = wx1 * wy1z0;
            float w100 = wx0 * wy0z1, w101 = wx1 * wy0z1;
            float w110 = wx0 * wy1z1, w111 = wx1 * wy1z1;

            f0 = w000*v000.x + w001*v001.x + w010*v010.x + w011*v011.x
               + w100*v100.x + w101*v101.x + w110*v110.x + w111*v111.x;
            f1 = w000*v000.y + w001*v001.y + w010*v010.y + w011*v011.y
               + w100*v100.y + w101*v101.y + w110*v110.y + w111*v111.y;
        }

        u64 f00 = pack2(f0, f0);
        u64 f11 = pack2(f1, f1);
        const u64* r0 = &w0[g << 6];
        const u64* r1 = r0 + 32;
#pragma unroll
        for (int j = 0; j < 32; ++j)
            acc0[j] = ffma2(f00, r0[j], ffma2(f11, r1[j], acc0[j]));
    }

    // relu -> h0
    float h0[64];
#pragma unroll
    for (int j = 0; j < 32; ++j) {
        float lo, hi; unpack2(acc0[j], lo, hi);
        h0[2*j]   = fmaxf(lo, 0.0f);
        h0[2*j+1] = fmaxf(hi, 0.0f);
    }

    // layer 1
    u64 acc1[32];
#pragma unroll
    for (int j = 0; j < 32; ++j) acc1[j] = 0ull;
#pragma unroll
    for (int k = 0; k < 64; ++k) {
        u64 hk = pack2(h0[k], h0[k]);
        const u64* row = &w1[k << 5];
#pragma unroll
        for (int j = 0; j < 32; ++j)
            acc1[j] = ffma2(hk, row[j], acc1[j]);
    }

    // layer 2
    float res = 0.0f;
#pragma unroll
    for (int j = 0; j < 32; ++j) {
        float lo, hi;  unpack2(acc1[j], lo, hi);
        float wl, wh;  unpack2(w2[j], wl, wh);
        res = fmaf(fmaxf(lo, 0.0f), wl, res);
        res = fmaf(fmaxf(hi, 0.0f), wh, res);
    }
    out[pdst] = res;
}

extern "C" void kernel_launch(void* const* d_in, const int* in_sizes, int n_in,
                              void* d_out, int out_size) {
    const float* x        = (const float*)d_in[0];
    const float* r        = (const float*)d_in[1];
    const float* s        = (const float*)d_in[2];
    const float* t        = (const float*)d_in[3];
    const float* features = (const float*)d_in[4];
    const float* W0       = (const float*)d_in[5];
    const float* W1       = (const float*)d_in[6];
    const float* W2       = (const float*)d_in[7];
    float* out = (float*)d_out;

    const int smem_bytes = 4096*8 + 2048*8 + 32*8 + 768*4;  // 52480
    cudaFuncSetAttribute(amgsrn_main, cudaFuncAttributeMaxDynamicSharedMemorySize, smem_bytes);

    amgsrn_prep<<<1, 256>>>(r, s, t, W0, W1, W2);
    amgsrn_relayout<<<(N_GRIDS * CH_OFF) / 256, 256>>>(features);
    amgsrn_zero_hist<<<(NB + 255) / 256, 256>>>();
    amgsrn_hist<<<N_PTS / 256, 256>>>(x);
    amgsrn_scan<<<1, 1024>>>();
    amgsrn_scatter<<<N_PTS / 256, 256>>>(x);
    amgsrn_main<<<N_PTS / 128, 128, smem_bytes>>>(nullptr, out);
}

// round 4
// speedup vs baseline: 2.0734x; 1.0494x over previous
#include <cuda_runtime.h>
#include <cuda_fp16.h>
#include <math.h>

#define N_PTS   (1 << 19)
#define N_GRIDS 64
#define CH_OFF  262144   // 64*64*64
#define NB      32768    // 32^3 morton buckets

typedef unsigned long long u64;

// ---------- packed f32x2 helpers ----------
__device__ __forceinline__ u64 pack2(float lo, float hi) {
    u64 r; asm("mov.b64 %0, {%1, %2};" : "=l"(r) : "f"(lo), "f"(hi)); return r;
}
__device__ __forceinline__ void unpack2(u64 v, float& lo, float& hi) {
    asm("mov.b64 {%0, %1}, %2;" : "=f"(lo), "=f"(hi) : "l"(v));
}
__device__ __forceinline__ u64 ffma2(u64 a, u64 b, u64 c) {
    u64 d; asm("fma.rn.f32x2 %0, %1, %2, %3;" : "=l"(d) : "l"(a), "l"(b), "l"(c)); return d;
}

// ---------- device scratch ----------
__device__ float   g_xf[N_GRIDS * 12];
__device__ float2  g_w0p[128 * 32];
__device__ float2  g_w1p[64 * 32];
__device__ float2  g_w2p[32];
__device__ __half2 g_feat16[N_GRIDS * CH_OFF];     // 67 MB: [g][zyx] -> (c0,c1)
__device__ __half2 g_featsP[(size_t)N_GRIDS * N_PTS]; // 134 MB: [g][sorted p] -> (f0,f1)
__device__ int     g_hist[NB];
__device__ int     g_off[NB];
__device__ int     g_perm[N_PTS];
__device__ float4  g_xs[N_PTS];

// ---------- prep: transforms + weight pair-packing ----------
__global__ void amgsrn_prep(const float* __restrict__ r, const float* __restrict__ s,
                            const float* __restrict__ t,
                            const float* __restrict__ W0, const float* __restrict__ W1,
                            const float* __restrict__ W2) {
    int tid = threadIdx.x;
    if (tid < N_GRIDS) {
        int g = tid;
        float qw = r[g*4+0], qx = r[g*4+1], qy = r[g*4+2], qz = r[g*4+3];
        float inv = rsqrtf(qw*qw + qx*qx + qy*qy + qz*qz);
        qw *= inv; qx *= inv; qy *= inv; qz *= inv;
        float sx = s[g*3+0], sy = s[g*3+1], sz = s[g*3+2];
        float* X = &g_xf[g*12];
        X[0] = sx * (1.0f - 2.0f*(qy*qy + qz*qz));
        X[1] = sx * (2.0f*(qx*qy - qw*qz));
        X[2] = sx * (2.0f*(qx*qz + qw*qy));
        X[3] = sy * (2.0f*(qx*qy + qw*qz));
        X[4] = sy * (1.0f - 2.0f*(qx*qx + qz*qz));
        X[5] = sy * (2.0f*(qy*qz - qw*qx));
        X[6] = sz * (2.0f*(qx*qz - qw*qy));
        X[7] = sz * (2.0f*(qy*qz + qw*qx));
        X[8] = sz * (1.0f - 2.0f*(qx*qx + qy*qy));
        X[9]  = t[g*3+0];
        X[10] = t[g*3+1];
        X[11] = t[g*3+2];
    }
    for (int i = tid; i < 128*32; i += blockDim.x) {
        int k = i >> 5, j2 = i & 31;
        g_w0p[i] = make_float2(W0[(2*j2)*128 + k], W0[(2*j2+1)*128 + k]);
    }
    for (int i = tid; i < 64*32; i += blockDim.x) {
        int k = i >> 5, j2 = i & 31;
        g_w1p[i] = make_float2(W1[(2*j2)*64 + k], W1[(2*j2+1)*64 + k]);
    }
    if (tid < 32) g_w2p[tid] = make_float2(W2[2*tid], W2[2*tid+1]);
}

// ---------- feature relayout: [g][c][zyx] fp32 -> [g][zyx] half2 ----------
__global__ void amgsrn_relayout(const float* __restrict__ features) {
    int i = blockIdx.x * 256 + threadIdx.x;
    int g = i >> 18;
    int v = i & (CH_OFF - 1);
    const float* b = features + (((size_t)g * 2) << 18) + v;
    g_feat16[i] = __floats2half2_rn(b[0], b[CH_OFF]);
}

// ---------- sort: morton bucket counting-sort ----------
__device__ __forceinline__ unsigned expand_bits(unsigned v) {
    v &= 0x3ff;
    v = (v | (v << 16)) & 0x030000FF;
    v = (v | (v << 8))  & 0x0300F00F;
    v = (v | (v << 4))  & 0x030C30C3;
    v = (v | (v << 2))  & 0x09249249;
    return v;
}
__device__ __forceinline__ int morton_bucket(float px, float py, float pz) {
    unsigned ux = (unsigned)min(max((int)((px + 1.0f) * 16.0f), 0), 31);
    unsigned uy = (unsigned)min(max((int)((py + 1.0f) * 16.0f), 0), 31);
    unsigned uz = (unsigned)min(max((int)((pz + 1.0f) * 16.0f), 0), 31);
    return (int)(expand_bits(ux) | (expand_bits(uy) << 1) | (expand_bits(uz) << 2));
}

__global__ void amgsrn_zero_hist() {
    int i = blockIdx.x * 256 + threadIdx.x;
    if (i < NB) g_hist[i] = 0;
}
__global__ void amgsrn_hist(const float* __restrict__ x) {
    int p = blockIdx.x * 256 + threadIdx.x;
    int b = morton_bucket(x[3*p], x[3*p+1], x[3*p+2]);
    atomicAdd(&g_hist[b], 1);
}
__global__ void amgsrn_scan() {
    __shared__ int partial[1024];
    int tid = threadIdx.x;
    int base = tid * 32;
    int loc[32];
    int sum = 0;
#pragma unroll
    for (int i = 0; i < 32; ++i) { loc[i] = sum; sum += g_hist[base + i]; }
    partial[tid] = sum;
    __syncthreads();
    for (int d = 1; d < 1024; d <<= 1) {
        int v = 0;
        if (tid >= d) v = partial[tid - d];
        __syncthreads();
        if (tid >= d) partial[tid] += v;
        __syncthreads();
    }
    int off = (tid > 0) ? partial[tid - 1] : 0;
#pragma unroll
    for (int i = 0; i < 32; ++i) g_off[base + i] = off + loc[i];
}
__global__ void amgsrn_scatter(const float* __restrict__ x) {
    int p = blockIdx.x * 256 + threadIdx.x;
    float px = x[3*p], py = x[3*p+1], pz = x[3*p+2];
    int b = morton_bucket(px, py, pz);
    int pos = atomicAdd(&g_off[b], 1);
    g_perm[pos] = p;
    g_xs[pos] = make_float4(px, py, pz, 0.0f);
}

// ---------- kernel A: gather/encode only (lean, high occupancy) ----------
__global__ void __launch_bounds__(128, 6)
amgsrn_gather() {
    __shared__ float xf[N_GRIDS * 12];
    int tid = threadIdx.x;
    for (int i = tid; i < N_GRIDS * 12; i += 128) xf[i] = g_xf[i];
    __syncthreads();

    int i = blockIdx.x * 128 + tid;
    float4 pt = g_xs[i];
    float px = pt.x, py = pt.y, pz = pt.z;

#pragma unroll 2
    for (int g = 0; g < N_GRIDS; ++g) {
        const float* X = &xf[g*12];
        float tpx = fmaf(X[0], px, fmaf(X[1], py, fmaf(X[2], pz, X[9])));
        float tpy = fmaf(X[3], px, fmaf(X[4], py, fmaf(X[5], pz, X[10])));
        float tpz = fmaf(X[6], px, fmaf(X[7], py, fmaf(X[8], pz, X[11])));
        float gx = (tpx + 1.0f) * 31.5f;
        float gy = (tpy + 1.0f) * 31.5f;
        float gz = (tpz + 1.0f) * 31.5f;
        bool inb = (gx > -1.0f) && (gx < 64.0f) &&
                   (gy > -1.0f) && (gy < 64.0f) &&
                   (gz > -1.0f) && (gz < 64.0f);

        float f0 = 0.0f, f1 = 0.0f;
        if (inb) {
            float x0f = floorf(gx), y0f = floorf(gy), z0f = floorf(gz);
            float fx = gx - x0f, fy = gy - y0f, fz = gz - z0f;
            int x0 = (int)x0f, y0 = (int)y0f, z0 = (int)z0f;
            float wx0 = (x0 >= 0) ? (1.0f - fx) : 0.0f;
            float wx1 = (x0 < 63) ? fx : 0.0f;
            float wy0 = (y0 >= 0) ? (1.0f - fy) : 0.0f;
            float wy1 = (y0 < 63) ? fy : 0.0f;
            float wz0 = (z0 >= 0) ? (1.0f - fz) : 0.0f;
            float wz1 = (z0 < 63) ? fz : 0.0f;
            int x0c = max(x0, 0), x1c = min(x0 + 1, 63);
            int y0c = max(y0, 0), y1c = min(y0 + 1, 63);
            int z0c = max(z0, 0), z1c = min(z0 + 1, 63);

            const __half2* fb = g_feat16 + ((size_t)g << 18);
            int r00 = (z0c << 12) + (y0c << 6);
            int r01 = (z0c << 12) + (y1c << 6);
            int r10 = (z1c << 12) + (y0c << 6);
            int r11 = (z1c << 12) + (y1c << 6);

            float2 v000 = __half22float2(__ldg(fb + r00 + x0c));
            float2 v001 = __half22float2(__ldg(fb + r00 + x1c));
            float2 v010 = __half22float2(__ldg(fb + r01 + x0c));
            float2 v011 = __half22float2(__ldg(fb + r01 + x1c));
            float2 v100 = __half22float2(__ldg(fb + r10 + x0c));
            float2 v101 = __half22float2(__ldg(fb + r10 + x1c));
            float2 v110 = __half22float2(__ldg(fb + r11 + x0c));
            float2 v111 = __half22float2(__ldg(fb + r11 + x1c));

            float wy0z0 = wy0 * wz0, wy1z0 = wy1 * wz0;
            float wy0z1 = wy0 * wz1, wy1z1 = wy1 * wz1;
            float w000 = wx0 * wy0z0, w001 = wx1 * wy0z0;
            float w010 = wx0 * wy1z0, w011 = wx1 * wy1z0;
            float w100 = wx0 * wy0z1, w101 = wx1 * wy0z1;
            float w110 = wx0 * wy1z1, w111 = wx1 * wy1z1;

            f0 = w000*v000.x + w001*v001.x + w010*v010.x + w011*v011.x
               + w100*v100.x + w101*v101.x + w110*v110.x + w111*v111.x;
            f1 = w000*v000.y + w001*v001.y + w010*v010.y + w011*v011.y
               + w100*v100.y + w101*v101.y + w110*v110.y + w111*v111.y;
        }
        g_featsP[((size_t)g << 19) + i] = __floats2half2_rn(f0, f1);
    }
}

// ---------- kernel B: MLP only (compute-bound FFMA2) ----------
__global__ void __launch_bounds__(128, 3)
amgsrn_mlp(float* __restrict__ out) {
    extern __shared__ float smem[];
    u64* w0 = (u64*)smem;           // 4096 u64 (32 KB)
    u64* w1 = w0 + 4096;            // 2048 u64 (16 KB)
    u64* w2 = w1 + 2048;            // 32 u64

    int tid = threadIdx.x;
    {
        const u64* s0 = (const u64*)g_w0p;
        for (int i = tid; i < 4096; i += 128) w0[i] = s0[i];
        const u64* s1 = (const u64*)g_w1p;
        for (int i = tid; i < 2048; i += 128) w1[i] = s1[i];
        if (tid < 32) w2[tid] = ((const u64*)g_w2p)[tid];
    }
    __syncthreads();

    int i = blockIdx.x * 128 + tid;

    u64 acc0[32];
#pragma unroll
    for (int j = 0; j < 32; ++j) acc0[j] = 0ull;

#pragma unroll 4
    for (int g = 0; g < N_GRIDS; ++g) {
        float2 f = __half22float2(g_featsP[((size_t)g << 19) + i]);
        u64 f00 = pack2(f.x, f.x);
        u64 f11 = pack2(f.y, f.y);
        const u64* r0 = &w0[g << 6];
        const u64* r1 = r0 + 32;
#pragma unroll
        for (int j = 0; j < 32; ++j)
            acc0[j] = ffma2(f00, r0[j], ffma2(f11, r1[j], acc0[j]));
    }

    // relu -> h0
    float h0[64];
#pragma unroll
    for (int j = 0; j < 32; ++j) {
        float lo, hi; unpack2(acc0[j], lo, hi);
        h0[2*j]   = fmaxf(lo, 0.0f);
        h0[2*j+1] = fmaxf(hi, 0.0f);
    }

    // layer 1
    u64 acc1[32];
#pragma unroll
    for (int j = 0; j < 32; ++j) acc1[j] = 0ull;
#pragma unroll
    for (int k = 0; k < 64; ++k) {
        u64 hk = pack2(h0[k], h0[k]);
        const u64* row = &w1[k << 5];
#pragma unroll
        for (int j = 0; j < 32; ++j)
            acc1[j] = ffma2(hk, row[j], acc1[j]);
    }

    // layer 2
    float res = 0.0f;
#pragma unroll
    for (int j = 0; j < 32; ++j) {
        float lo, hi;  unpack2(acc1[j], lo, hi);
        float wl, wh;  unpack2(w2[j], wl, wh);
        res = fmaf(fmaxf(lo, 0.0f), wl, res);
        res = fmaf(fmaxf(hi, 0.0f), wh, res);
    }
    out[g_perm[i]] = res;
}

extern "C" void kernel_launch(void* const* d_in, const int* in_sizes, int n_in,
                              void* d_out, int out_size) {
    const float* x        = (const float*)d_in[0];
    const float* r        = (const float*)d_in[1];
    const float* s        = (const float*)d_in[2];
    const float* t        = (const float*)d_in[3];
    const float* features = (const float*)d_in[4];
    const float* W0       = (const float*)d_in[5];
    const float* W1       = (const float*)d_in[6];
    const float* W2       = (const float*)d_in[7];
    float* out = (float*)d_out;

    const int smem_mlp = 4096*8 + 2048*8 + 32*8;  // 49408
    cudaFuncSetAttribute(amgsrn_mlp, cudaFuncAttributeMaxDynamicSharedMemorySize, smem_mlp);

    amgsrn_prep<<<1, 256>>>(r, s, t, W0, W1, W2);
    amgsrn_relayout<<<(N_GRIDS * CH_OFF) / 256, 256>>>(features);
    amgsrn_zero_hist<<<(NB + 255) / 256, 256>>>();
    amgsrn_hist<<<N_PTS / 256, 256>>>(x);
    amgsrn_scan<<<1, 1024>>>();
    amgsrn_scatter<<<N_PTS / 256, 256>>>(x);
    amgsrn_gather<<<N_PTS / 128, 128>>>();
    amgsrn_mlp<<<N_PTS / 128, 128, smem_mlp>>>(out);
}